// round 16
// baseline (speedup 1.0000x reference)
#include <cuda_runtime.h>
#include <cuda_fp16.h>
#include <math.h>

#define BI 256
#define BH 512
#define BC 1024
#define G4 2048
#define TYN 32
#define TXN 128
#define BB 32

#define NBLK 128
#define NTHR 768   // 24 warps
#define NWRP 24

// scan smem layout (float slots)
#define OFF_U    0        // U rows   [16][512]
#define OFF_WX   8192     // Wx rows  [16][1024]
#define OFF_PART 24576    // partials [16][8][32]
#define OFF_GS   28672    // gsum     [16][32]
#define OFF_UA2  29184    // uatt2    [512] (u32)
#define OFF_WT   29696    // per-warp softmax wt [24][128]
#define SMEM_FLOATS 32768
#define SMEM_BYTES (SMEM_FLOATS * 4)   // 131072

typedef unsigned long long u64t;

// ---------------- device scratch ----------------
__device__ __align__(16) unsigned g_pctx2[(size_t)TXN * BB * 512];  // [t'*32+b][c2] f16x2
__device__ float  g_xT[(size_t)TYN * G4 * BB];     // [t][g][b]
__device__ float4 g_hT4[128 * 32];                 // h carry [k4][b]
__device__ float4 g_act4[384 * 32];                // [h1 | atted] [k4][b]
__device__ float  g_cT[BH * BB];                   // c carry [h][b]
__device__ float  g_c1T[BH * BB];
__device__ __align__(16) float g_hpp[4][BB * BC];  // hproj k-chunk partials [ch][b][d]
__device__ float  g_p2a[4][G4 * BB];               // Ux.h1 k-chunk partials [ch][row][b]
__device__ __align__(16) float g_scoreQ[BB * 512]; // [b][t'*4+q]
__device__ float  g_xmT[BB * TXN];                 // x_mask [b][t']
__device__ __align__(16) unsigned g_uatt2[512];
__device__ unsigned g_cnt1[16];
__device__ unsigned g_cnt2;
__device__ unsigned g_flag;
__device__ unsigned g_gcnt[32 * 32];   // per-group counters (128B apart)
__device__ unsigned g_gflag[32 * 32];  // per-group release flags

__device__ __forceinline__ float sigf(float x) { return 1.f / (1.f + __expf(-x)); }
__device__ __forceinline__ __half2 tanh2(__half2 x) {
    unsigned xi = *(unsigned*)&x, ri;
    asm("tanh.approx.f16x2 %0, %1;" : "=r"(ri) : "r"(xi));
    return *(__half2*)&ri;
}
__device__ __forceinline__ u64t ffma2(u64t a, u64t b, u64t c) {
    u64t d; asm("fma.rn.f32x2 %0, %1, %2, %3;" : "=l"(d) : "l"(a), "l"(b), "l"(c));
    return d;
}
__device__ __forceinline__ float fsum2(u64t v) {
    float lo, hi; asm("mov.b64 {%0, %1}, %2;" : "=f"(lo), "=f"(hi) : "l"(v));
    return lo + hi;
}
__device__ __forceinline__ unsigned ldacq(const unsigned* p) {
    unsigned v;
    asm volatile("ld.acquire.gpu.global.u32 %0, [%1];" : "=r"(v) : "l"(p) : "memory");
    return v;
}

// 16-group two-level grid barrier (128 blocks = 16 x 8)
__device__ __forceinline__ void gbar(int beta) {
    __syncthreads();
    if (threadIdx.x == 0) {
        __threadfence();
        const int p = beta & 15;
        unsigned a = atomicAdd(&g_cnt1[p], 1u);
        unsigned epoch = (a >> 3) + 1u;
        if ((a & 7u) == 7u) {
            unsigned b = atomicAdd(&g_cnt2, 1u);
            if ((b & 15u) == 15u) {
                unsigned e = (b >> 4) + 1u;
                asm volatile("red.release.gpu.global.max.u32 [%0], %1;"
                             :: "l"(&g_flag), "r"(e) : "memory");
            }
        }
        while (ldacq(&g_flag) < epoch) { }
    }
    __syncthreads();
}

// 4-block group barrier
__device__ __forceinline__ void groupbar(int grp) {
    __syncthreads();
    if (threadIdx.x == 0) {
        __threadfence();
        unsigned a = atomicAdd(&g_gcnt[grp * 32], 1u);
        unsigned epoch = (a >> 2) + 1u;
        if ((a & 3u) == 3u) {
            asm volatile("red.release.gpu.global.max.u32 [%0], %1;"
                         :: "l"(&g_gflag[grp * 32]), "r"(epoch) : "memory");
        }
        while (ldacq(&g_gflag[grp * 32]) < epoch) { }
    }
    __syncthreads();
}

// ---------------- tensor-core helpers ----------------
__device__ __forceinline__ void ldsm4(unsigned* r, unsigned addr) {
    asm volatile("ldmatrix.sync.aligned.m8n8.x4.shared.b16 {%0,%1,%2,%3}, [%4];"
                 : "=r"(r[0]), "=r"(r[1]), "=r"(r[2]), "=r"(r[3]) : "r"(addr));
}
__device__ __forceinline__ void mma16816(float* c, const unsigned* a, const unsigned* b) {
    asm volatile("mma.sync.aligned.m16n8k16.row.col.f32.f16.f16.f32 "
                 "{%0,%1,%2,%3}, {%4,%5,%6,%7}, {%8,%9}, {%0,%1,%2,%3};"
                 : "+f"(c[0]), "+f"(c[1]), "+f"(c[2]), "+f"(c[3])
                 : "r"(a[0]), "r"(a[1]), "r"(a[2]), "r"(a[3]), "r"(b[0]), "r"(b[1]));
}

// ---------------- fused GEMM: pctx via HMMA (bid<256) + xT via FFMA2 ----------
#define PADK 40   // f16 elements per smem row (80B)

__global__ void __launch_bounds__(256) gemm_fused(const float* __restrict__ context,
                                                  const float* __restrict__ Wc_att,
                                                  const float* __restrict__ y_emb,
                                                  const float* __restrict__ W) {
    __shared__ __align__(16) char sraw[2 * 2 * 128 * PADK * 2];  // 40960 B

    const int bid = blockIdx.x;
    const int tid = threadIdx.x;

    if (bid < 256) {
        // ================= HMMA pctx =================
        const int w = tid >> 5, lane = tid & 31;
        const int m0 = (bid >> 3) * 128;
        const int n0 = (bid & 7) * 128;
        const int wm = (w >> 1) * 32;
        const int wn = (w & 1) * 64;

        __half* Ah = (__half*)sraw;                       // [2][128][PADK]
        __half* Bh = (__half*)sraw + 2 * 128 * PADK;      // [2][128][PADK]

        const int lr = tid >> 1, lhalf = tid & 1;
        const float* Ag = context + (size_t)(m0 + lr) * 1024 + lhalf * 16;
        const float* Bg = Wc_att  + (size_t)(n0 + lr) * 1024 + lhalf * 16;

        const unsigned abase = (unsigned)__cvta_generic_to_shared(Ah);
        const unsigned bbase = (unsigned)__cvta_generic_to_shared(Bh);
        const int arow = wm + (lane & 15);
        const int acol = (lane >> 4) * 8;
        const int brow = wn + ((lane >> 4) << 3) + (lane & 7);
        const int bcol = ((lane >> 3) & 1) * 8;

        float acc[2][8][4];
#pragma unroll
        for (int mt = 0; mt < 2; ++mt)
#pragma unroll
            for (int nt = 0; nt < 8; ++nt)
#pragma unroll
                for (int i = 0; i < 4; ++i) acc[mt][nt][i] = 0.f;

        auto store16 = [&](__half* dst, const float4* v) {
            __half2 h[8];
#pragma unroll
            for (int i = 0; i < 4; ++i) {
                h[2 * i]     = __floats2half2_rn(v[i].x, v[i].y);
                h[2 * i + 1] = __floats2half2_rn(v[i].z, v[i].w);
            }
            *(uint4*)dst = *(uint4*)&h[0];
            *(uint4*)(dst + 8) = *(uint4*)&h[4];
        };

        {
            float4 va[4], vb[4];
#pragma unroll
            for (int i = 0; i < 4; ++i) { va[i] = *(const float4*)(Ag + i * 4); vb[i] = *(const float4*)(Bg + i * 4); }
            store16(Ah + lr * PADK + lhalf * 16, va);
            store16(Bh + lr * PADK + lhalf * 16, vb);
        }
        __syncthreads();

#pragma unroll 1
        for (int ks = 0; ks < 32; ++ks) {
            const int cur = ks & 1;
            float4 pa[4], pb[4];
            const bool more = (ks + 1 < 32);
            if (more) {
                const int kg = (ks + 1) * 32;
#pragma unroll
                for (int i = 0; i < 4; ++i) {
                    pa[i] = *(const float4*)(Ag + kg + i * 4);
                    pb[i] = *(const float4*)(Bg + kg + i * 4);
                }
            }
            const unsigned aoff = abase + (unsigned)(cur * 128 * PADK * 2);
            const unsigned boff = bbase + (unsigned)(cur * 128 * PADK * 2);
#pragma unroll
            for (int kk = 0; kk < 2; ++kk) {
                unsigned afr[2][4];
                ldsm4(afr[0], aoff + (unsigned)(((arow)      * PADK + kk * 16 + acol) * 2));
                ldsm4(afr[1], aoff + (unsigned)(((arow + 16) * PADK + kk * 16 + acol) * 2));
                unsigned bfr[4][4];
#pragma unroll
                for (int jp = 0; jp < 4; ++jp)
                    ldsm4(bfr[jp], boff + (unsigned)(((brow + jp * 16) * PADK + kk * 16 + bcol) * 2));
#pragma unroll
                for (int mt = 0; mt < 2; ++mt)
#pragma unroll
                    for (int nt = 0; nt < 8; ++nt) {
                        unsigned bb[2] = { bfr[nt >> 1][(nt & 1) * 2], bfr[nt >> 1][(nt & 1) * 2 + 1] };
                        mma16816(acc[mt][nt], afr[mt], bb);
                    }
            }
            if (more) {
                const int nxt = cur ^ 1;
                store16(Ah + nxt * 128 * PADK + lr * PADK + lhalf * 16, pa);
                store16(Bh + nxt * 128 * PADK + lr * PADK + lhalf * 16, pb);
                __syncthreads();
            }
        }

        const int qrow = lane >> 2;
        const int qcol = lane & 3;
#pragma unroll
        for (int mt = 0; mt < 2; ++mt) {
#pragma unroll
            for (int nt = 0; nt < 8; ++nt) {
                const int c2 = (n0 + wn + nt * 8) / 2 + qcol;
                const int m1 = m0 + wm + mt * 16 + qrow;
                __half2 lo = __floats2half2_rn(acc[mt][nt][0], acc[mt][nt][1]);
                __half2 hi = __floats2half2_rn(acc[mt][nt][2], acc[mt][nt][3]);
                g_pctx2[(size_t)m1 * 512 + c2]       = *(unsigned*)&lo;
                g_pctx2[(size_t)(m1 + 8) * 512 + c2] = *(unsigned*)&hi;
            }
        }
    } else {
        // ================= FFMA2 xT =================
        float* Asf = (float*)sraw;              // [2][8][128]
        float* Bsf = (float*)(sraw + 8192);     // [2][8][128]
        const int b2 = bid - 256;
        const int m0 = (b2 >> 4) * 128;
        const int n0 = (b2 & 15) * 128;
        const int K = 256;

        const int tm = (tid / 16) * 8;
        const int tn = (tid % 16) * 8;
        const int lr = tid >> 1;
        const int lc = (tid & 1) * 4;

        const float* Aptr = y_emb + (size_t)(m0 + lr) * K + lc;
        const float* Bptr = W     + (size_t)(n0 + lr) * K + lc;

        float acc[8][8];
#pragma unroll
        for (int i = 0; i < 8; ++i)
#pragma unroll
            for (int j = 0; j < 8; ++j) acc[i][j] = 0.f;

        {
            float4 av = *(const float4*)(Aptr);
            float4 bv = *(const float4*)(Bptr);
            Asf[(lc + 0) * 128 + lr] = av.x; Asf[(lc + 1) * 128 + lr] = av.y;
            Asf[(lc + 2) * 128 + lr] = av.z; Asf[(lc + 3) * 128 + lr] = av.w;
            Bsf[(lc + 0) * 128 + lr] = bv.x; Bsf[(lc + 1) * 128 + lr] = bv.y;
            Bsf[(lc + 2) * 128 + lr] = bv.z; Bsf[(lc + 3) * 128 + lr] = bv.w;
        }
        __syncthreads();

        const int T = K / 8;
        int cur = 0;
#pragma unroll 1
        for (int kk = 0; kk < T; ++kk) {
            float4 av, bv;
            const bool more = (kk + 1 < T);
            if (more) {
                av = *(const float4*)(Aptr + (kk + 1) * 8);
                bv = *(const float4*)(Bptr + (kk + 1) * 8);
            }
            const float* Ac = Asf + cur * 1024;
            const float* Bc = Bsf + cur * 1024;
#pragma unroll
            for (int k = 0; k < 8; ++k) {
                float ar[8], br[8];
                *(float4*)(ar)     = *(const float4*)&Ac[k * 128 + tm];
                *(float4*)(ar + 4) = *(const float4*)&Ac[k * 128 + tm + 4];
                *(float4*)(br)     = *(const float4*)&Bc[k * 128 + tn];
                *(float4*)(br + 4) = *(const float4*)&Bc[k * 128 + tn + 4];
#pragma unroll
                for (int i = 0; i < 8; ++i)
#pragma unroll
                    for (int j = 0; j < 8; ++j)
                        acc[i][j] = fmaf(ar[i], br[j], acc[i][j]);
            }
            if (more) {
                const int nxt = cur ^ 1;
                float* An = Asf + nxt * 1024;
                float* Bn = Bsf + nxt * 1024;
                An[(lc + 0) * 128 + lr] = av.x; An[(lc + 1) * 128 + lr] = av.y;
                An[(lc + 2) * 128 + lr] = av.z; An[(lc + 3) * 128 + lr] = av.w;
                Bn[(lc + 0) * 128 + lr] = bv.x; Bn[(lc + 1) * 128 + lr] = bv.y;
                Bn[(lc + 2) * 128 + lr] = bv.z; Bn[(lc + 3) * 128 + lr] = bv.w;
                __syncthreads();
                cur = nxt;
            }
        }

#pragma unroll
        for (int i = 0; i < 8; ++i) {
            const int m = m0 + tm + i;
            const int t = m >> 5, b = m & 31;
            float* base = g_xT + (size_t)t * (G4 * BB) + b;
#pragma unroll
            for (int j = 0; j < 8; ++j)
                base[(size_t)(n0 + tn + j) * BB] = acc[i][j];
        }
    }
}

// dot4: 4 rows x act slice
template<int NK4>
__device__ __forceinline__ void dot4(const ulonglong2* __restrict__ actp,
                                     const ulonglong2* __restrict__ base,
                                     int rowstride_u2, u64t acc[4]) {
#pragma unroll 4
    for (int k = 0; k < NK4; ++k) {
        ulonglong2 a = actp[k * 32];
        ulonglong2 w0 = base[k];
        ulonglong2 w1 = base[rowstride_u2 + k];
        ulonglong2 w2 = base[2 * rowstride_u2 + k];
        ulonglong2 w3 = base[3 * rowstride_u2 + k];
        acc[0] = ffma2(a.x, w0.x, acc[0]); acc[0] = ffma2(a.y, w0.y, acc[0]);
        acc[1] = ffma2(a.x, w1.x, acc[1]); acc[1] = ffma2(a.y, w1.y, acc[1]);
        acc[2] = ffma2(a.x, w2.x, acc[2]); acc[2] = ffma2(a.y, w2.y, acc[2]);
        acc[3] = ffma2(a.x, w3.x, acc[3]); acc[3] = ffma2(a.y, w3.y, acc[3]);
    }
}

// ---------------- persistent scan kernel v16: 4 global barriers/step ----------
__global__ void __launch_bounds__(NTHR, 1) scan_kernel(
    const float* __restrict__ context,
    const float* __restrict__ init_h, const float* __restrict__ init_c,
    const float* __restrict__ x_mask, const float* __restrict__ y_mask,
    const float* __restrict__ U, const float* __restrict__ bvec,
    const float* __restrict__ Wx, const float* __restrict__ Ux,
    const float* __restrict__ bx, const float* __restrict__ b_att,
    const float* __restrict__ Wcomb, const float* __restrict__ Uatt,
    float* __restrict__ out)
{
    extern __shared__ __align__(16) float smw[];
    unsigned* smwu = (unsigned*)smw;

    const int ltid = threadIdx.x;
    const int w = ltid >> 5;
    const int lane = ltid & 31;
    const int beta = blockIdx.x;
    const int gtid = beta * NTHR + ltid;
    const int gw = w * NBLK + beta;      // 0..3071
    const int grp = beta >> 2;           // group = batch element b
    const int wig = (beta & 3) * NWRP + w;   // warp-in-group 0..95

    float* out_hs = out;
    float* out_cs = out + TYN * BB * BH;
    float* out_atts = out + 2 * TYN * BB * BH;

    float* hT = (float*)g_hT4;
    float* actF = (float*)g_act4;

    for (int i = gtid; i < BB * BH; i += NBLK * NTHR) {
        int k = i >> 5, b = i & 31;
        hT[(k >> 2) * 128 + b * 4 + (k & 3)] = init_h[b * BH + k];
        g_cT[k * 32 + b] = init_c[b * BH + k];
    }
    if (gtid < 512) {
        __half2 hv = __floats2half2_rn(Uatt[2 * gtid], Uatt[2 * gtid + 1]);
        g_uatt2[gtid] = *(unsigned*)&hv;
    }
    for (int i = gtid; i < TXN * BB; i += NBLK * NTHR)
        g_xmT[(i & 31) * TXN + (i >> 5)] = x_mask[i];
    gbar(beta);

    // one-time weight staging (first 16 warps)
    if (w < 16) {
        const int gate = w >> 2, hc = w & 3;
        const float* usrc  = U  + ((size_t)gate * BH + (beta << 2) + hc) * BH;
        const float* wxsrc = Wx + ((size_t)gate * BH + (beta << 2) + hc) * BC;
#pragma unroll
        for (int i = 0; i < 4; ++i)
            *(float4*)&smw[OFF_U  + w * 512 + i * 128 + lane * 4] = *(const float4*)(usrc  + i * 128 + lane * 4);
#pragma unroll
        for (int i = 0; i < 8; ++i)
            *(float4*)&smw[OFF_WX + w * 1024 + i * 128 + lane * 4] = *(const float4*)(wxsrc + i * 128 + lane * 4);
    }
    if (ltid < 512) smwu[OFF_UA2 + ltid] = g_uatt2[ltid];
    __syncthreads();

    const int rg = w >> 3;   // (valid for w<16)
    const int sp = w & 7;

    for (int t = 0; t < TYN; ++t) {
        // ===== P1: pre1 = hT . U (smem, 16 warps) + cell1 =====
        if (w < 16) {
            u64t acc[8];
#pragma unroll
            for (int r = 0; r < 8; ++r) acc[r] = 0ull;
            const ulonglong2* actp = (const ulonglong2*)g_hT4 + (sp * 16) * 32 + lane;
            const int wbase = OFF_U + (rg * 8) * 512 + sp * 64;
#pragma unroll 4
            for (int k4 = 0; k4 < 16; ++k4) {
                ulonglong2 a = actp[k4 * 32];
#pragma unroll
                for (int r = 0; r < 8; ++r) {
                    ulonglong2 wv = *(const ulonglong2*)&smw[wbase + r * 512 + k4 * 4];
                    acc[r] = ffma2(a.x, wv.x, acc[r]);
                    acc[r] = ffma2(a.y, wv.y, acc[r]);
                }
            }
#pragma unroll
            for (int r = 0; r < 8; ++r)
                smw[OFF_PART + (rg * 8 + r) * 256 + sp * 32 + lane] = fsum2(acc[r]);
        }
        __syncthreads();
        if (w < 16) {
            float v = 0.f;
#pragma unroll
            for (int s8 = 0; s8 < 8; ++s8) v += smw[OFF_PART + w * 256 + s8 * 32 + lane];
            smw[OFF_GS + w * 32 + lane] = v;
        }
        __syncthreads();
        if (w < 4) {
            const int hh = (beta << 2) + w;
            const float* xt = g_xT + (size_t)t * (G4 * BB);
            float pi = smw[OFF_GS + (0 * 4 + w) * 32 + lane] + xt[(0 * BH + hh) * BB + lane] + bvec[hh];
            float pf = smw[OFF_GS + (1 * 4 + w) * 32 + lane] + xt[(1 * BH + hh) * BB + lane] + bvec[BH + hh];
            float po = smw[OFF_GS + (2 * 4 + w) * 32 + lane] + xt[(2 * BH + hh) * BB + lane] + bvec[2 * BH + hh];
            float pg = smw[OFF_GS + (3 * 4 + w) * 32 + lane] + xt[(3 * BH + hh) * BB + lane] + bvec[3 * BH + hh];
            float cold = g_cT[hh * 32 + lane];
            float hold = hT[(hh >> 2) * 128 + lane * 4 + (hh & 3)];
            float c1 = sigf(pf) * cold + sigf(pi) * tanhf(pg);
            float h1v = sigf(po) * tanhf(c1);
            float ym = y_mask[t * BB + lane];
            h1v = ym * h1v + (1.f - ym) * hold;
            g_c1T[hh * 32 + lane] = c1;
            actF[(hh >> 2) * 128 + lane * 4 + (hh & 3)] = h1v;
        }
        gbar(beta);

        // ===== W2: hproj quartets (1024) + Ux.h1 quartets (2048), 1 task/warp =====
        if (gw < 1024) {
            const int o = gw >> 2, ch = gw & 3;
            u64t acc[4];
#pragma unroll
            for (int r = 0; r < 4; ++r) acc[r] = 0ull;
            const ulonglong2* actp = (const ulonglong2*)g_act4 + (ch * 32) * 32 + lane;
            const ulonglong2* b0 = (const ulonglong2*)(Wcomb + (size_t)(o * 4) * BH) + ch * 32;
            dot4<32>(actp, b0, BH / 4, acc);
            float* dst = g_hpp[ch] + lane * BC + o * 4;
#pragma unroll
            for (int r = 0; r < 4; ++r) {
                float v = fsum2(acc[r]);
                if (ch == 0) v += b_att[o * 4 + r];
                dst[r] = v;
            }
        } else {
            const int q2 = gw - 1024;
            const int o = q2 >> 2, ch = q2 & 3;
            u64t acc[4];
#pragma unroll
            for (int r = 0; r < 4; ++r) acc[r] = 0ull;
            const ulonglong2* actp = (const ulonglong2*)g_act4 + (ch * 32) * 32 + lane;
            const ulonglong2* b0 = (const ulonglong2*)(Ux + (size_t)(o * 4) * BH) + ch * 32;
            dot4<32>(actp, b0, BH / 4, acc);
            float* dst = g_p2a[ch] + (size_t)(o * 4) * 32 + lane;
#pragma unroll
            for (int r = 0; r < 4; ++r) dst[r * 32] = fsum2(acc[r]);
        }
        gbar(beta);

        // ===== P3+P4 (group-local): scores for b=grp, group sync, atted =====
        {
            const int b = grp;
            const int q = wig & 3;               // fixed per warp
            // hoist hpp + uatt for this (b, q)
            const int hoff = b * BC + q * 256 + lane * 8;
            float4 p0a = *(const float4*)(g_hpp[0] + hoff);
            float4 p0b = *(const float4*)(g_hpp[0] + hoff + 4);
            float4 p1a = *(const float4*)(g_hpp[1] + hoff);
            float4 p1b = *(const float4*)(g_hpp[1] + hoff + 4);
            float4 p2a = *(const float4*)(g_hpp[2] + hoff);
            float4 p2b = *(const float4*)(g_hpp[2] + hoff + 4);
            float4 p3a = *(const float4*)(g_hpp[3] + hoff);
            float4 p3b = *(const float4*)(g_hpp[3] + hoff + 4);
            uint4 ua = *(const uint4*)(smwu + OFF_UA2 + q * 128 + lane * 4);
            __half2 hp0 = __floats2half2_rn((p0a.x + p1a.x) + (p2a.x + p3a.x),
                                            (p0a.y + p1a.y) + (p2a.y + p3a.y));
            __half2 hp1 = __floats2half2_rn((p0a.z + p1a.z) + (p2a.z + p3a.z),
                                            (p0a.w + p1a.w) + (p2a.w + p3a.w));
            __half2 hp2 = __floats2half2_rn((p0b.x + p1b.x) + (p2b.x + p3b.x),
                                            (p0b.y + p1b.y) + (p2b.y + p3b.y));
            __half2 hp3 = __floats2half2_rn((p0b.z + p1b.z) + (p2b.z + p3b.z),
                                            (p0b.w + p1b.w) + (p2b.w + p3b.w));
#pragma unroll 1
            for (int tau = wig; tau < 512; tau += 96) {
                const int tp = tau >> 2;
                const int s = tp * 32 + b;
                uint4 pc = *(const uint4*)(g_pctx2 + (size_t)s * 512 + q * 128 + lane * 4);
                __half2 acc2 = __floats2half2_rn(0.f, 0.f);
                acc2 = __hfma2(*(__half2*)&ua.x, tanh2(__hadd2(*(__half2*)&pc.x, hp0)), acc2);
                acc2 = __hfma2(*(__half2*)&ua.y, tanh2(__hadd2(*(__half2*)&pc.y, hp1)), acc2);
                acc2 = __hfma2(*(__half2*)&ua.z, tanh2(__hadd2(*(__half2*)&pc.z, hp2)), acc2);
                acc2 = __hfma2(*(__half2*)&ua.w, tanh2(__hadd2(*(__half2*)&pc.w, hp3)), acc2);
                float2 f2 = __half22float2(acc2);
                float v = f2.x + f2.y;
#pragma unroll
                for (int o2 = 16; o2; o2 >>= 1) v += __shfl_xor_sync(0xffffffffu, v, o2);
                if (lane == 0) g_scoreQ[b * 512 + tp * 4 + q] = v;
            }

            groupbar(grp);

            // atted[b]: warps 64..95 (these had 5 score tasks)
            if (wig >= 64) {
                const int c = (wig - 64) * 32 + lane;
                float sc[4], xm[4];
#pragma unroll
                for (int j = 0; j < 4; ++j) {
                    float4 vq = *(const float4*)&g_scoreQ[b * 512 + (lane + 32 * j) * 4];
                    xm[j] = g_xmT[b * TXN + lane + 32 * j];
                    sc[j] = ((vq.x + vq.y) + (vq.z + vq.w)) * xm[j];
                }
                float mx = fmaxf(fmaxf(sc[0], sc[1]), fmaxf(sc[2], sc[3]));
#pragma unroll
                for (int o2 = 16; o2; o2 >>= 1) mx = fmaxf(mx, __shfl_xor_sync(0xffffffffu, mx, o2));
                float e[4], sm = 0.f;
#pragma unroll
                for (int j = 0; j < 4; ++j) { e[j] = __expf(sc[j] - mx) * xm[j]; sm += e[j]; }
#pragma unroll
                for (int o2 = 16; o2; o2 >>= 1) sm += __shfl_xor_sync(0xffffffffu, sm, o2);
                const float inv = 1.f / sm;
#pragma unroll
                for (int j = 0; j < 4; ++j) smw[OFF_WT + w * 128 + lane + 32 * j] = e[j] * inv;
                __syncwarp();
                const float* ctxp = context + (size_t)b * BC + c;
                const float* wp = smw + OFF_WT + w * 128;
                float a0 = 0.f, a1 = 0.f, a2 = 0.f, a3 = 0.f;
#pragma unroll 8
                for (int tp = 0; tp < TXN; tp += 4) {
                    a0 = fmaf(wp[tp + 0], ctxp[(size_t)(tp + 0) * (BB * BC)], a0);
                    a1 = fmaf(wp[tp + 1], ctxp[(size_t)(tp + 1) * (BB * BC)], a1);
                    a2 = fmaf(wp[tp + 2], ctxp[(size_t)(tp + 2) * (BB * BC)], a2);
                    a3 = fmaf(wp[tp + 3], ctxp[(size_t)(tp + 3) * (BB * BC)], a3);
                }
                const float av = (a0 + a1) + (a2 + a3);
                out_atts[(size_t)t * (BB * BC) + b * BC + c] = av;
                actF[(128 + (c >> 2)) * 128 + b * 4 + (c & 3)] = av;
            }
        }
        gbar(beta);

        // ===== P5: Wx.atted (smem, 16 warps) + p2a + cell2 =====
        if (w < 16) {
            u64t acc[8];
#pragma unroll
            for (int r = 0; r < 8; ++r) acc[r] = 0ull;
            const ulonglong2* actp = (const ulonglong2*)g_act4 + (128 + sp * 32) * 32 + lane;
            const int wbase = OFF_WX + (rg * 8) * 1024 + sp * 128;
#pragma unroll 4
            for (int k4 = 0; k4 < 32; ++k4) {
                ulonglong2 a = actp[k4 * 32];
#pragma unroll
                for (int r = 0; r < 8; ++r) {
                    ulonglong2 wv = *(const ulonglong2*)&smw[wbase + r * 1024 + k4 * 4];
                    acc[r] = ffma2(a.x, wv.x, acc[r]);
                    acc[r] = ffma2(a.y, wv.y, acc[r]);
                }
            }
#pragma unroll
            for (int r = 0; r < 8; ++r)
                smw[OFF_PART + (rg * 8 + r) * 256 + sp * 32 + lane] = fsum2(acc[r]);
        }
        __syncthreads();
        if (w < 16) {
            float v = 0.f;
#pragma unroll
            for (int s8 = 0; s8 < 8; ++s8) v += smw[OFF_PART + w * 256 + s8 * 32 + lane];
            smw[OFF_GS + w * 32 + lane] = v;
        }
        __syncthreads();
        if (w < 4) {
            const int hh = (beta << 2) + w;
            float pg4[4];
#pragma unroll
            for (int g = 0; g < 4; ++g) {
                const int row = g * BH + hh;
                float v = smw[OFF_GS + (g * 4 + w) * 32 + lane] + bx[row];
                v += g_p2a[0][(size_t)row * 32 + lane];
                v += g_p2a[1][(size_t)row * 32 + lane];
                v += g_p2a[2][(size_t)row * 32 + lane];
                v += g_p2a[3][(size_t)row * 32 + lane];
                pg4[g] = v;
            }
            float c1 = g_c1T[hh * 32 + lane];
            float h1v = actF[(hh >> 2) * 128 + lane * 4 + (hh & 3)];
            float c2 = sigf(pg4[1]) * c1 + sigf(pg4[0]) * tanhf(pg4[3]);
            float h2 = sigf(pg4[2]) * tanhf(c2);
            float ym = y_mask[t * BB + lane];
            h2 = ym * h2 + (1.f - ym) * h1v;
            out_hs[(size_t)t * (BB * BH) + lane * BH + hh] = h2;
            out_cs[(size_t)t * (BB * BH) + lane * BH + hh] = c2;
            g_cT[hh * 32 + lane] = c2;
            hT[(hh >> 2) * 128 + lane * 4 + (hh & 3)] = h2;
        }
        gbar(beta);
    }
}

// ---------------- launch ----------------
extern "C" void kernel_launch(void* const* d_in, const int* in_sizes, int n_in,
                              void* d_out, int out_size) {
    const float* y_emb   = (const float*)d_in[0];
    const float* context = (const float*)d_in[1];
    const float* init_h  = (const float*)d_in[2];
    const float* init_c  = (const float*)d_in[3];
    const float* x_mask  = (const float*)d_in[4];
    const float* y_mask  = (const float*)d_in[5];
    const float* W       = (const float*)d_in[6];
    const float* U       = (const float*)d_in[7];
    const float* bvec    = (const float*)d_in[8];
    const float* Wx      = (const float*)d_in[9];
    const float* Ux      = (const float*)d_in[10];
    const float* bx      = (const float*)d_in[11];
    const float* Wc_att  = (const float*)d_in[12];
    const float* b_att   = (const float*)d_in[13];
    const float* Wcomb   = (const float*)d_in[14];
    const float* Uatt    = (const float*)d_in[15];

    cudaFuncSetAttribute(scan_kernel, cudaFuncAttributeMaxDynamicSharedMemorySize, SMEM_BYTES);

    gemm_fused<<<384, 256>>>(context, Wc_att, y_emb, W);

    scan_kernel<<<NBLK, NTHR, SMEM_BYTES>>>(context, init_h, init_c, x_mask, y_mask,
                                            U, bvec, Wx, Ux, bx, b_att, Wcomb, Uatt,
                                            (float*)d_out);
}

// round 17
// speedup vs baseline: 1.0664x; 1.0664x over previous
#include <cuda_runtime.h>
#include <cuda_fp16.h>
#include <math.h>

#define BI 256
#define BH 512
#define BC 1024
#define G4 2048
#define TYN 32
#define TXN 128
#define BB 32

#define NBLK 148
#define NTHR 768   // 24 warps
#define NWRP 24

// scan smem layout (float slots)
#define OFF_U    0        // U rows   [16][512]
#define OFF_WX   8192     // Wx rows  [16][1024]
#define OFF_PART 24576    // partials [16][8][32]
#define OFF_GS   28672    // gsum     [16][32]
#define OFF_UA2  29184    // uatt2    [512] (u32)
#define OFF_WT   29696    // per-warp softmax wt [24][128]
#define SMEM_FLOATS 32768
#define SMEM_BYTES (SMEM_FLOATS * 4)   // 131072

typedef unsigned long long u64t;

// ---------------- device scratch ----------------
__device__ __align__(16) unsigned g_pctx2[(size_t)TXN * BB * 512];  // [t'*32+b][c2] f16x2
__device__ float  g_xT[(size_t)TYN * G4 * BB];     // [t][g][b]
__device__ float4 g_hT4[128 * 32];                 // h carry [k4][b]
__device__ float4 g_act4[384 * 32];                // [h1 | atted] [k4][b]
__device__ float  g_cT[BH * BB];                   // c carry [h][b]
__device__ float  g_c1T[BH * BB];
__device__ __align__(16) float g_hpp[4][BB * BC];  // hproj k-chunk partials [ch][b][d]
__device__ float  g_p2a[4][G4 * BB];               // Ux.h1 k-chunk partials [ch][row][b]
__device__ __align__(16) float g_scoreQ[BB * 512]; // [b][t'*4+q]
__device__ float  g_xmT[BB * TXN];                 // x_mask [b][t']
__device__ __align__(16) unsigned g_uatt2[512];
__device__ unsigned g_cnt1[16];
__device__ unsigned g_cnt2;
__device__ unsigned g_flag;

__device__ __forceinline__ float sigf(float x) { return 1.f / (1.f + __expf(-x)); }
__device__ __forceinline__ __half2 tanh2(__half2 x) {
    unsigned xi = *(unsigned*)&x, ri;
    asm("tanh.approx.f16x2 %0, %1;" : "=r"(ri) : "r"(xi));
    return *(__half2*)&ri;
}
__device__ __forceinline__ u64t ffma2(u64t a, u64t b, u64t c) {
    u64t d; asm("fma.rn.f32x2 %0, %1, %2, %3;" : "=l"(d) : "l"(a), "l"(b), "l"(c));
    return d;
}
__device__ __forceinline__ u64t pack2(float lo, float hi) {
    u64t v; asm("mov.b64 %0, {%1, %2};" : "=l"(v) : "f"(lo), "f"(hi));
    return v;
}
__device__ __forceinline__ float fsum2(u64t v) {
    float lo, hi; asm("mov.b64 {%0, %1}, %2;" : "=f"(lo), "=f"(hi) : "l"(v));
    return lo + hi;
}
__device__ __forceinline__ unsigned ldacq(const unsigned* p) {
    unsigned v;
    asm volatile("ld.acquire.gpu.global.u32 %0, [%1];" : "=r"(v) : "l"(p) : "memory");
    return v;
}

// 16-group two-level grid barrier
__device__ __forceinline__ void gbar(int beta) {
    __syncthreads();
    if (threadIdx.x == 0) {
        __threadfence();
        const int p = beta & 15;
        const unsigned cnt = (p < 4) ? 10u : 9u;   // 148 = 4*10 + 12*9
        unsigned a = atomicAdd(&g_cnt1[p], 1u);
        unsigned epoch = a / cnt + 1u;
        if (a % cnt == cnt - 1u) {
            unsigned b = atomicAdd(&g_cnt2, 1u);
            if ((b & 15u) == 15u) {
                unsigned e = (b >> 4) + 1u;
                asm volatile("red.release.gpu.global.max.u32 [%0], %1;"
                             :: "l"(&g_flag), "r"(e) : "memory");
            }
        }
        while (ldacq(&g_flag) < epoch) { }
    }
    __syncthreads();
}

// ---------------- tensor-core helpers ----------------
__device__ __forceinline__ void ldsm4(unsigned* r, unsigned addr) {
    asm volatile("ldmatrix.sync.aligned.m8n8.x4.shared.b16 {%0,%1,%2,%3}, [%4];"
                 : "=r"(r[0]), "=r"(r[1]), "=r"(r[2]), "=r"(r[3]) : "r"(addr));
}
__device__ __forceinline__ void mma16816(float* c, const unsigned* a, const unsigned* b) {
    asm volatile("mma.sync.aligned.m16n8k16.row.col.f32.f16.f16.f32 "
                 "{%0,%1,%2,%3}, {%4,%5,%6,%7}, {%8,%9}, {%0,%1,%2,%3};"
                 : "+f"(c[0]), "+f"(c[1]), "+f"(c[2]), "+f"(c[3])
                 : "r"(a[0]), "r"(a[1]), "r"(a[2]), "r"(a[3]), "r"(b[0]), "r"(b[1]));
}

// ---------------- fused GEMM: pctx via HMMA (bid<256) + xT via FFMA2 ----------
#define PADK 40   // f16 elements per smem row (80B)

__global__ void __launch_bounds__(256) gemm_fused(const float* __restrict__ context,
                                                  const float* __restrict__ Wc_att,
                                                  const float* __restrict__ y_emb,
                                                  const float* __restrict__ W) {
    __shared__ __align__(16) char sraw[2 * 2 * 128 * PADK * 2];  // 40960 B

    const int bid = blockIdx.x;
    const int tid = threadIdx.x;

    if (bid < 256) {
        // ================= HMMA pctx =================
        const int w = tid >> 5, lane = tid & 31;
        const int m0 = (bid >> 3) * 128;
        const int n0 = (bid & 7) * 128;
        const int wm = (w >> 1) * 32;
        const int wn = (w & 1) * 64;

        __half* Ah = (__half*)sraw;                       // [2][128][PADK]
        __half* Bh = (__half*)sraw + 2 * 128 * PADK;      // [2][128][PADK]

        const int lr = tid >> 1, lhalf = tid & 1;
        const float* Ag = context + (size_t)(m0 + lr) * 1024 + lhalf * 16;
        const float* Bg = Wc_att  + (size_t)(n0 + lr) * 1024 + lhalf * 16;

        const unsigned abase = (unsigned)__cvta_generic_to_shared(Ah);
        const unsigned bbase = (unsigned)__cvta_generic_to_shared(Bh);
        const int arow = wm + (lane & 15);
        const int acol = (lane >> 4) * 8;
        const int brow = wn + ((lane >> 4) << 3) + (lane & 7);
        const int bcol = ((lane >> 3) & 1) * 8;

        float acc[2][8][4];
#pragma unroll
        for (int mt = 0; mt < 2; ++mt)
#pragma unroll
            for (int nt = 0; nt < 8; ++nt)
#pragma unroll
                for (int i = 0; i < 4; ++i) acc[mt][nt][i] = 0.f;

        auto store16 = [&](__half* dst, const float4* v) {
            __half2 h[8];
#pragma unroll
            for (int i = 0; i < 4; ++i) {
                h[2 * i]     = __floats2half2_rn(v[i].x, v[i].y);
                h[2 * i + 1] = __floats2half2_rn(v[i].z, v[i].w);
            }
            *(uint4*)dst = *(uint4*)&h[0];
            *(uint4*)(dst + 8) = *(uint4*)&h[4];
        };

        {
            float4 va[4], vb[4];
#pragma unroll
            for (int i = 0; i < 4; ++i) { va[i] = *(const float4*)(Ag + i * 4); vb[i] = *(const float4*)(Bg + i * 4); }
            store16(Ah + lr * PADK + lhalf * 16, va);
            store16(Bh + lr * PADK + lhalf * 16, vb);
        }
        __syncthreads();

#pragma unroll 1
        for (int ks = 0; ks < 32; ++ks) {
            const int cur = ks & 1;
            float4 pa[4], pb[4];
            const bool more = (ks + 1 < 32);
            if (more) {
                const int kg = (ks + 1) * 32;
#pragma unroll
                for (int i = 0; i < 4; ++i) {
                    pa[i] = *(const float4*)(Ag + kg + i * 4);
                    pb[i] = *(const float4*)(Bg + kg + i * 4);
                }
            }
            const unsigned aoff = abase + (unsigned)(cur * 128 * PADK * 2);
            const unsigned boff = bbase + (unsigned)(cur * 128 * PADK * 2);
#pragma unroll
            for (int kk = 0; kk < 2; ++kk) {
                unsigned afr[2][4];
                ldsm4(afr[0], aoff + (unsigned)(((arow)      * PADK + kk * 16 + acol) * 2));
                ldsm4(afr[1], aoff + (unsigned)(((arow + 16) * PADK + kk * 16 + acol) * 2));
                unsigned bfr[4][4];
#pragma unroll
                for (int jp = 0; jp < 4; ++jp)
                    ldsm4(bfr[jp], boff + (unsigned)(((brow + jp * 16) * PADK + kk * 16 + bcol) * 2));
#pragma unroll
                for (int mt = 0; mt < 2; ++mt)
#pragma unroll
                    for (int nt = 0; nt < 8; ++nt) {
                        unsigned bb[2] = { bfr[nt >> 1][(nt & 1) * 2], bfr[nt >> 1][(nt & 1) * 2 + 1] };
                        mma16816(acc[mt][nt], afr[mt], bb);
                    }
            }
            if (more) {
                const int nxt = cur ^ 1;
                store16(Ah + nxt * 128 * PADK + lr * PADK + lhalf * 16, pa);
                store16(Bh + nxt * 128 * PADK + lr * PADK + lhalf * 16, pb);
                __syncthreads();
            }
        }

        const int qrow = lane >> 2;
        const int qcol = lane & 3;
#pragma unroll
        for (int mt = 0; mt < 2; ++mt) {
#pragma unroll
            for (int nt = 0; nt < 8; ++nt) {
                const int c2 = (n0 + wn + nt * 8) / 2 + qcol;
                const int m1 = m0 + wm + mt * 16 + qrow;
                __half2 lo = __floats2half2_rn(acc[mt][nt][0], acc[mt][nt][1]);
                __half2 hi = __floats2half2_rn(acc[mt][nt][2], acc[mt][nt][3]);
                g_pctx2[(size_t)m1 * 512 + c2]       = *(unsigned*)&lo;
                g_pctx2[(size_t)(m1 + 8) * 512 + c2] = *(unsigned*)&hi;
            }
        }
    } else {
        // ================= FFMA2 xT =================
        float* Asf = (float*)sraw;              // [2][8][128]
        float* Bsf = (float*)(sraw + 8192);     // [2][8][128]
        const int b2 = bid - 256;
        const int m0 = (b2 >> 4) * 128;
        const int n0 = (b2 & 15) * 128;
        const int K = 256;

        const int tm = (tid / 16) * 8;
        const int tn = (tid % 16) * 8;
        const int lr = tid >> 1;
        const int lc = (tid & 1) * 4;

        const float* Aptr = y_emb + (size_t)(m0 + lr) * K + lc;
        const float* Bptr = W     + (size_t)(n0 + lr) * K + lc;

        float acc[8][8];
#pragma unroll
        for (int i = 0; i < 8; ++i)
#pragma unroll
            for (int j = 0; j < 8; ++j) acc[i][j] = 0.f;

        {
            float4 av = *(const float4*)(Aptr);
            float4 bv = *(const float4*)(Bptr);
            Asf[(lc + 0) * 128 + lr] = av.x; Asf[(lc + 1) * 128 + lr] = av.y;
            Asf[(lc + 2) * 128 + lr] = av.z; Asf[(lc + 3) * 128 + lr] = av.w;
            Bsf[(lc + 0) * 128 + lr] = bv.x; Bsf[(lc + 1) * 128 + lr] = bv.y;
            Bsf[(lc + 2) * 128 + lr] = bv.z; Bsf[(lc + 3) * 128 + lr] = bv.w;
        }
        __syncthreads();

        const int T = K / 8;
        int cur = 0;
#pragma unroll 1
        for (int kk = 0; kk < T; ++kk) {
            float4 av, bv;
            const bool more = (kk + 1 < T);
            if (more) {
                av = *(const float4*)(Aptr + (kk + 1) * 8);
                bv = *(const float4*)(Bptr + (kk + 1) * 8);
            }
            const float* Ac = Asf + cur * 1024;
            const float* Bc = Bsf + cur * 1024;
#pragma unroll
            for (int k = 0; k < 8; ++k) {
                float ar[8], br[8];
                *(float4*)(ar)     = *(const float4*)&Ac[k * 128 + tm];
                *(float4*)(ar + 4) = *(const float4*)&Ac[k * 128 + tm + 4];
                *(float4*)(br)     = *(const float4*)&Bc[k * 128 + tn];
                *(float4*)(br + 4) = *(const float4*)&Bc[k * 128 + tn + 4];
#pragma unroll
                for (int i = 0; i < 8; ++i)
#pragma unroll
                    for (int j = 0; j < 8; ++j)
                        acc[i][j] = fmaf(ar[i], br[j], acc[i][j]);
            }
            if (more) {
                const int nxt = cur ^ 1;
                float* An = Asf + nxt * 1024;
                float* Bn = Bsf + nxt * 1024;
                An[(lc + 0) * 128 + lr] = av.x; An[(lc + 1) * 128 + lr] = av.y;
                An[(lc + 2) * 128 + lr] = av.z; An[(lc + 3) * 128 + lr] = av.w;
                Bn[(lc + 0) * 128 + lr] = bv.x; Bn[(lc + 1) * 128 + lr] = bv.y;
                Bn[(lc + 2) * 128 + lr] = bv.z; Bn[(lc + 3) * 128 + lr] = bv.w;
                __syncthreads();
                cur = nxt;
            }
        }

#pragma unroll
        for (int i = 0; i < 8; ++i) {
            const int m = m0 + tm + i;
            const int t = m >> 5, b = m & 31;
            float* base = g_xT + (size_t)t * (G4 * BB) + b;
#pragma unroll
            for (int j = 0; j < 8; ++j)
                base[(size_t)(n0 + tn + j) * BB] = acc[i][j];
        }
    }
}

// dot4: 4 rows x act slice
template<int NK4>
__device__ __forceinline__ void dot4(const ulonglong2* __restrict__ actp,
                                     const ulonglong2* __restrict__ base,
                                     int rowstride_u2, u64t acc[4]) {
#pragma unroll 4
    for (int k = 0; k < NK4; ++k) {
        ulonglong2 a = actp[k * 32];
        ulonglong2 w0 = base[k];
        ulonglong2 w1 = base[rowstride_u2 + k];
        ulonglong2 w2 = base[2 * rowstride_u2 + k];
        ulonglong2 w3 = base[3 * rowstride_u2 + k];
        acc[0] = ffma2(a.x, w0.x, acc[0]); acc[0] = ffma2(a.y, w0.y, acc[0]);
        acc[1] = ffma2(a.x, w1.x, acc[1]); acc[1] = ffma2(a.y, w1.y, acc[1]);
        acc[2] = ffma2(a.x, w2.x, acc[2]); acc[2] = ffma2(a.y, w2.y, acc[2]);
        acc[3] = ffma2(a.x, w3.x, acc[3]); acc[3] = ffma2(a.y, w3.y, acc[3]);
    }
}

// ---------------- persistent scan kernel (R12 champion) ----------------
__global__ void __launch_bounds__(NTHR, 1) scan_kernel(
    const float* __restrict__ context,
    const float* __restrict__ init_h, const float* __restrict__ init_c,
    const float* __restrict__ x_mask, const float* __restrict__ y_mask,
    const float* __restrict__ U, const float* __restrict__ bvec,
    const float* __restrict__ Wx, const float* __restrict__ Ux,
    const float* __restrict__ bx, const float* __restrict__ b_att,
    const float* __restrict__ Wcomb, const float* __restrict__ Uatt,
    float* __restrict__ out)
{
    extern __shared__ __align__(16) float smw[];
    unsigned* smwu = (unsigned*)smw;

    const int ltid = threadIdx.x;
    const int w = ltid >> 5;
    const int lane = ltid & 31;
    const int beta = blockIdx.x;
    const int gtid = beta * NTHR + ltid;
    const int gw = w * NBLK + beta;      // 0..3551

    float* out_hs = out;
    float* out_cs = out + TYN * BB * BH;
    float* out_atts = out + 2 * TYN * BB * BH;

    float* hT = (float*)g_hT4;
    float* actF = (float*)g_act4;

    for (int i = gtid; i < BB * BH; i += NBLK * NTHR) {
        int k = i >> 5, b = i & 31;
        hT[(k >> 2) * 128 + b * 4 + (k & 3)] = init_h[b * BH + k];
        g_cT[k * 32 + b] = init_c[b * BH + k];
    }
    if (gtid < 512) {
        __half2 hv = __floats2half2_rn(Uatt[2 * gtid], Uatt[2 * gtid + 1]);
        g_uatt2[gtid] = *(unsigned*)&hv;
    }
    for (int i = gtid; i < TXN * BB; i += NBLK * NTHR)
        g_xmT[(i & 31) * TXN + (i >> 5)] = x_mask[i];
    gbar(beta);

    // one-time weight staging (first 16 warps)
    if (beta < 128 && w < 16) {
        const int gate = w >> 2, hc = w & 3;
        const float* usrc  = U  + ((size_t)gate * BH + (beta << 2) + hc) * BH;
        const float* wxsrc = Wx + ((size_t)gate * BH + (beta << 2) + hc) * BC;
#pragma unroll
        for (int i = 0; i < 4; ++i)
            *(float4*)&smw[OFF_U  + w * 512 + i * 128 + lane * 4] = *(const float4*)(usrc  + i * 128 + lane * 4);
#pragma unroll
        for (int i = 0; i < 8; ++i)
            *(float4*)&smw[OFF_WX + w * 1024 + i * 128 + lane * 4] = *(const float4*)(wxsrc + i * 128 + lane * 4);
    }
    if (ltid < 512) smwu[OFF_UA2 + ltid] = g_uatt2[ltid];
    __syncthreads();

    const int rg = w >> 3;   // (valid for w<16)
    const int sp = w & 7;

    for (int t = 0; t < TYN; ++t) {
        // ===== P1: pre1 = hT . U (smem, 16 warps) + cell1 =====
        if (beta < 128 && w < 16) {
            u64t acc[8];
#pragma unroll
            for (int r = 0; r < 8; ++r) acc[r] = 0ull;
            const ulonglong2* actp = (const ulonglong2*)g_hT4 + (sp * 16) * 32 + lane;
            const int wbase = OFF_U + (rg * 8) * 512 + sp * 64;
#pragma unroll 4
            for (int k4 = 0; k4 < 16; ++k4) {
                ulonglong2 a = actp[k4 * 32];
#pragma unroll
                for (int r = 0; r < 8; ++r) {
                    ulonglong2 wv = *(const ulonglong2*)&smw[wbase + r * 512 + k4 * 4];
                    acc[r] = ffma2(a.x, wv.x, acc[r]);
                    acc[r] = ffma2(a.y, wv.y, acc[r]);
                }
            }
#pragma unroll
            for (int r = 0; r < 8; ++r)
                smw[OFF_PART + (rg * 8 + r) * 256 + sp * 32 + lane] = fsum2(acc[r]);
        }
        __syncthreads();
        if (beta < 128 && w < 16) {
            float v = 0.f;
#pragma unroll
            for (int s8 = 0; s8 < 8; ++s8) v += smw[OFF_PART + w * 256 + s8 * 32 + lane];
            smw[OFF_GS + w * 32 + lane] = v;
        }
        __syncthreads();
        if (beta < 128 && w < 4) {
            const int hh = (beta << 2) + w;
            const float* xt = g_xT + (size_t)t * (G4 * BB);
            float pi = smw[OFF_GS + (0 * 4 + w) * 32 + lane] + xt[(0 * BH + hh) * BB + lane] + bvec[hh];
            float pf = smw[OFF_GS + (1 * 4 + w) * 32 + lane] + xt[(1 * BH + hh) * BB + lane] + bvec[BH + hh];
            float po = smw[OFF_GS + (2 * 4 + w) * 32 + lane] + xt[(2 * BH + hh) * BB + lane] + bvec[2 * BH + hh];
            float pg = smw[OFF_GS + (3 * 4 + w) * 32 + lane] + xt[(3 * BH + hh) * BB + lane] + bvec[3 * BH + hh];
            float cold = g_cT[hh * 32 + lane];
            float hold = hT[(hh >> 2) * 128 + lane * 4 + (hh & 3)];
            float c1 = sigf(pf) * cold + sigf(pi) * tanhf(pg);
            float h1v = sigf(po) * tanhf(c1);
            float ym = y_mask[t * BB + lane];
            h1v = ym * h1v + (1.f - ym) * hold;
            g_c1T[hh * 32 + lane] = c1;
            actF[(hh >> 2) * 128 + lane * 4 + (hh & 3)] = h1v;
        }
        gbar(beta);

        // ===== W2: hproj quartets (1024 tasks) + Ux.h1 quartets (2048 tasks) =====
        if (gw < 1024) {
            const int o = gw >> 2, ch = gw & 3;
            u64t acc[4];
#pragma unroll
            for (int r = 0; r < 4; ++r) acc[r] = 0ull;
            const ulonglong2* actp = (const ulonglong2*)g_act4 + (ch * 32) * 32 + lane;
            const ulonglong2* b0 = (const ulonglong2*)(Wcomb + (size_t)(o * 4) * BH) + ch * 32;
            dot4<32>(actp, b0, BH / 4, acc);
            float* dst = g_hpp[ch] + lane * BC + o * 4;
#pragma unroll
            for (int r = 0; r < 4; ++r) {
                float v = fsum2(acc[r]);
                if (ch == 0) v += b_att[o * 4 + r];
                dst[r] = v;
            }
        } else if (gw < 3072) {
            const int q2 = gw - 1024;
            const int o = q2 >> 2, ch = q2 & 3;
            u64t acc[4];
#pragma unroll
            for (int r = 0; r < 4; ++r) acc[r] = 0ull;
            const ulonglong2* actp = (const ulonglong2*)g_act4 + (ch * 32) * 32 + lane;
            const ulonglong2* b0 = (const ulonglong2*)(Ux + (size_t)(o * 4) * BH) + ch * 32;
            dot4<32>(actp, b0, BH / 4, acc);
            float* dst = g_p2a[ch] + (size_t)(o * 4) * 32 + lane;
#pragma unroll
            for (int r = 0; r < 4; ++r) dst[r * 32] = fsum2(acc[r]);
        }
        gbar(beta);

        // ===== P3: scores via tanh.f16x2 =====
#pragma unroll 1
        for (int task = gw; task < 16384; task += NBLK * NWRP) {
            const int s = task >> 2, q = task & 3, b = s & 31;
            uint4 pc = *(const uint4*)(g_pctx2 + (size_t)s * 512 + q * 128 + lane * 4);
            const int hoff = b * BC + q * 256 + lane * 8;
            float4 p0a = *(const float4*)(g_hpp[0] + hoff);
            float4 p0b = *(const float4*)(g_hpp[0] + hoff + 4);
            float4 p1a = *(const float4*)(g_hpp[1] + hoff);
            float4 p1b = *(const float4*)(g_hpp[1] + hoff + 4);
            float4 p2a = *(const float4*)(g_hpp[2] + hoff);
            float4 p2b = *(const float4*)(g_hpp[2] + hoff + 4);
            float4 p3a = *(const float4*)(g_hpp[3] + hoff);
            float4 p3b = *(const float4*)(g_hpp[3] + hoff + 4);
            uint4 ua = *(const uint4*)(smwu + OFF_UA2 + q * 128 + lane * 4);
            __half2 hp0 = __floats2half2_rn((p0a.x + p1a.x) + (p2a.x + p3a.x),
                                            (p0a.y + p1a.y) + (p2a.y + p3a.y));
            __half2 hp1 = __floats2half2_rn((p0a.z + p1a.z) + (p2a.z + p3a.z),
                                            (p0a.w + p1a.w) + (p2a.w + p3a.w));
            __half2 hp2 = __floats2half2_rn((p0b.x + p1b.x) + (p2b.x + p3b.x),
                                            (p0b.y + p1b.y) + (p2b.y + p3b.y));
            __half2 hp3 = __floats2half2_rn((p0b.z + p1b.z) + (p2b.z + p3b.z),
                                            (p0b.w + p1b.w) + (p2b.w + p3b.w));
            __half2 acc2 = __floats2half2_rn(0.f, 0.f);
            acc2 = __hfma2(*(__half2*)&ua.x, tanh2(__hadd2(*(__half2*)&pc.x, hp0)), acc2);
            acc2 = __hfma2(*(__half2*)&ua.y, tanh2(__hadd2(*(__half2*)&pc.y, hp1)), acc2);
            acc2 = __hfma2(*(__half2*)&ua.z, tanh2(__hadd2(*(__half2*)&pc.z, hp2)), acc2);
            acc2 = __hfma2(*(__half2*)&ua.w, tanh2(__hadd2(*(__half2*)&pc.w, hp3)), acc2);
            float2 f2 = __half22float2(acc2);
            float v = f2.x + f2.y;
#pragma unroll
            for (int o2 = 16; o2; o2 >>= 1) v += __shfl_xor_sync(0xffffffffu, v, o2);
            if (lane == 0) g_scoreQ[b * 512 + (s >> 5) * 4 + q] = v;
        }
        gbar(beta);

        // ===== P4: per-task softmax + atted =====
        if (gw < 1024) {
            const int b = gw >> 5;
            const int c = (gw & 31) * 32 + lane;
            float sc[4], xm[4];
#pragma unroll
            for (int j = 0; j < 4; ++j) {
                float4 vq = *(const float4*)&g_scoreQ[b * 512 + (lane + 32 * j) * 4];
                xm[j] = g_xmT[b * TXN + lane + 32 * j];
                sc[j] = ((vq.x + vq.y) + (vq.z + vq.w)) * xm[j];
            }
            float mx = fmaxf(fmaxf(sc[0], sc[1]), fmaxf(sc[2], sc[3]));
#pragma unroll
            for (int o2 = 16; o2; o2 >>= 1) mx = fmaxf(mx, __shfl_xor_sync(0xffffffffu, mx, o2));
            float e[4], sm = 0.f;
#pragma unroll
            for (int j = 0; j < 4; ++j) { e[j] = __expf(sc[j] - mx) * xm[j]; sm += e[j]; }
#pragma unroll
            for (int o2 = 16; o2; o2 >>= 1) sm += __shfl_xor_sync(0xffffffffu, sm, o2);
            const float inv = 1.f / sm;
#pragma unroll
            for (int j = 0; j < 4; ++j) smw[OFF_WT + w * 128 + lane + 32 * j] = e[j] * inv;
            __syncwarp();
            const float* ctxp = context + (size_t)b * BC + c;
            const float* wp = smw + OFF_WT + w * 128;
            float a0 = 0.f, a1 = 0.f, a2 = 0.f, a3 = 0.f;
#pragma unroll 8
            for (int tp = 0; tp < TXN; tp += 4) {
                a0 = fmaf(wp[tp + 0], ctxp[(size_t)(tp + 0) * (BB * BC)], a0);
                a1 = fmaf(wp[tp + 1], ctxp[(size_t)(tp + 1) * (BB * BC)], a1);
                a2 = fmaf(wp[tp + 2], ctxp[(size_t)(tp + 2) * (BB * BC)], a2);
                a3 = fmaf(wp[tp + 3], ctxp[(size_t)(tp + 3) * (BB * BC)], a3);
            }
            const float av = (a0 + a1) + (a2 + a3);
            out_atts[(size_t)t * (BB * BC) + b * BC + c] = av;
            actF[(128 + (c >> 2)) * 128 + b * 4 + (c & 3)] = av;
        }
        gbar(beta);

        // ===== P5: Wx.atted (smem, 16 warps) + p2a + cell2 =====
        if (beta < 128 && w < 16) {
            u64t acc[8];
#pragma unroll
            for (int r = 0; r < 8; ++r) acc[r] = 0ull;
            const ulonglong2* actp = (const ulonglong2*)g_act4 + (128 + sp * 32) * 32 + lane;
            const int wbase = OFF_WX + (rg * 8) * 1024 + sp * 128;
#pragma unroll 4
            for (int k4 = 0; k4 < 32; ++k4) {
                ulonglong2 a = actp[k4 * 32];
#pragma unroll
                for (int r = 0; r < 8; ++r) {
                    ulonglong2 wv = *(const ulonglong2*)&smw[wbase + r * 1024 + k4 * 4];
                    acc[r] = ffma2(a.x, wv.x, acc[r]);
                    acc[r] = ffma2(a.y, wv.y, acc[r]);
                }
            }
#pragma unroll
            for (int r = 0; r < 8; ++r)
                smw[OFF_PART + (rg * 8 + r) * 256 + sp * 32 + lane] = fsum2(acc[r]);
        }
        __syncthreads();
        if (beta < 128 && w < 16) {
            float v = 0.f;
#pragma unroll
            for (int s8 = 0; s8 < 8; ++s8) v += smw[OFF_PART + w * 256 + s8 * 32 + lane];
            smw[OFF_GS + w * 32 + lane] = v;
        }
        __syncthreads();
        if (beta < 128 && w < 4) {
            const int hh = (beta << 2) + w;
            float pg4[4];
#pragma unroll
            for (int g = 0; g < 4; ++g) {
                const int row = g * BH + hh;
                float v = smw[OFF_GS + (g * 4 + w) * 32 + lane] + bx[row];
                v += g_p2a[0][(size_t)row * 32 + lane];
                v += g_p2a[1][(size_t)row * 32 + lane];
                v += g_p2a[2][(size_t)row * 32 + lane];
                v += g_p2a[3][(size_t)row * 32 + lane];
                pg4[g] = v;
            }
            float c1 = g_c1T[hh * 32 + lane];
            float h1v = actF[(hh >> 2) * 128 + lane * 4 + (hh & 3)];
            float c2 = sigf(pg4[1]) * c1 + sigf(pg4[0]) * tanhf(pg4[3]);
            float h2 = sigf(pg4[2]) * tanhf(c2);
            float ym = y_mask[t * BB + lane];
            h2 = ym * h2 + (1.f - ym) * h1v;
            out_hs[(size_t)t * (BB * BH) + lane * BH + hh] = h2;
            out_cs[(size_t)t * (BB * BH) + lane * BH + hh] = c2;
            g_cT[hh * 32 + lane] = c2;
            hT[(hh >> 2) * 128 + lane * 4 + (hh & 3)] = h2;
        }
        gbar(beta);
    }
}

// ---------------- launch ----------------
extern "C" void kernel_launch(void* const* d_in, const int* in_sizes, int n_in,
                              void* d_out, int out_size) {
    const float* y_emb   = (const float*)d_in[0];
    const float* context = (const float*)d_in[1];
    const float* init_h  = (const float*)d_in[2];
    const float* init_c  = (const float*)d_in[3];
    const float* x_mask  = (const float*)d_in[4];
    const float* y_mask  = (const float*)d_in[5];
    const float* W       = (const float*)d_in[6];
    const float* U       = (const float*)d_in[7];
    const float* bvec    = (const float*)d_in[8];
    const float* Wx      = (const float*)d_in[9];
    const float* Ux      = (const float*)d_in[10];
    const float* bx      = (const float*)d_in[11];
    const float* Wc_att  = (const float*)d_in[12];
    const float* b_att   = (const float*)d_in[13];
    const float* Wcomb   = (const float*)d_in[14];
    const float* Uatt    = (const float*)d_in[15];

    cudaFuncSetAttribute(scan_kernel, cudaFuncAttributeMaxDynamicSharedMemorySize, SMEM_BYTES);

    gemm_fused<<<384, 256>>>(context, Wc_att, y_emb, W);

    scan_kernel<<<NBLK, NTHR, SMEM_BYTES>>>(context, init_h, init_c, x_mask, y_mask,
                                            U, bvec, Wx, Ux, bx, b_att, Wcomb, Uatt,
                                            (float*)d_out);
}